// round 3
// baseline (speedup 1.0000x reference)
#include <cuda_runtime.h>

// Problem constants: B=8, CIN=COUT=128, H=W=64
#define NB   8
#define NC   128
#define NH   64
#define NW   64

// Scratch (device globals — no allocation allowed)
__device__ __align__(16) float g_xt[NB * NH * NW * NC];   // NHWC input, 16 MB
__device__ __align__(16) float g_off[NB * NH * NW * 4];   // shift_y, shift_x, scale1, scale2
__device__ __align__(16) float g_wt2[9 * 64 * 256];       // [k][cp][o][j]: w[o][2cp+j][k]

__constant__ float c_BY[9] = {-1,-1,-1, 0,0,0, 1,1,1};
__constant__ float c_BX[9] = {-1, 0, 1,-1,0,1,-1,0,1};

// ---------------------------------------------------------------------------
// mbarrier helpers
// ---------------------------------------------------------------------------
__device__ __forceinline__ unsigned smaddr(const void* p) {
    return (unsigned)__cvta_generic_to_shared(p);
}
__device__ __forceinline__ void mb_init(unsigned a, unsigned cnt) {
    asm volatile("mbarrier.init.shared.b64 [%0], %1;" :: "r"(a), "r"(cnt) : "memory");
}
__device__ __forceinline__ void mb_arrive(unsigned a) {
    asm volatile("mbarrier.arrive.shared.b64 _, [%0];" :: "r"(a) : "memory");
}
__device__ __forceinline__ void mb_wait(unsigned a, unsigned ph) {
    asm volatile(
        "{\n\t"
        ".reg .pred P;\n\t"
        "WL%=:\n\t"
        "mbarrier.try_wait.parity.acquire.cta.shared::cta.b64 P, [%0], %1, 0x989680;\n\t"
        "@!P bra WL%=;\n\t"
        "}" :: "r"(a), "r"(ph) : "memory");
}

// ---------------------------------------------------------------------------
// Kernel 1: NCHW -> NHWC transpose
// ---------------------------------------------------------------------------
__global__ void k_transpose(const float* __restrict__ x) {
    __shared__ float tile[32][33];
    int bh = blockIdx.x;
    int b = bh >> 6, h = bh & 63;
    int c0 = blockIdx.y * 32;
    int w0 = blockIdx.z * 32;
    int tx = threadIdx.x, ty = threadIdx.y;
#pragma unroll
    for (int q = 0; q < 4; q++) {
        int c = c0 + ty + 8 * q;
        tile[ty + 8 * q][tx] = x[(((b * NC + c) * NH + h) * NW) + w0 + tx];
    }
    __syncthreads();
#pragma unroll
    for (int q = 0; q < 4; q++) {
        int w = w0 + ty + 8 * q;
        g_xt[((b * NH + h) * NW + w) * NC + c0 + tx] = tile[tx][ty + 8 * q];
    }
}

// ---------------------------------------------------------------------------
// Kernel 2: w[o][c][k] -> g_wt2[k][cp][o][j] = w[o][2cp+j][k]  (channel pairs)
// ---------------------------------------------------------------------------
__global__ void k_wt2(const float* __restrict__ w) {
    int i = blockIdx.x * 256 + threadIdx.x;
    if (i < 9 * 64 * 256) {
        int k = i / 16384;
        int r = i & 16383;
        int cp = r >> 8;
        int o = (r >> 1) & 127;
        int j = r & 1;
        g_wt2[i] = w[(o * NC + 2 * cp + j) * 9 + k];
    }
}

// ---------------------------------------------------------------------------
// Kernel 3: offset conv -> g_off (unchanged from R1)
// ---------------------------------------------------------------------------
extern __shared__ float dsm[];
__global__ void __launch_bounds__(256) k_off(const float* __restrict__ w_off,
                                             const float* __restrict__ b_off) {
    float* xin = dsm;                  // [3][64][128]
    float* sw  = dsm + 3 * NW * NC;    // [4][9][128]
    int h = blockIdx.x, b = blockIdx.y;
    int t = threadIdx.x;

    for (int r = 0; r < 3; r++) {
        int hr = h + r - 1;
        float4* dst = (float4*)(xin + r * NW * NC);
        if (hr >= 0 && hr < NH) {
            const float4* src = (const float4*)(g_xt + ((b * NH + hr) * NW) * NC);
            for (int i = t; i < (NW * NC) / 4; i += 256) dst[i] = src[i];
        } else {
            for (int i = t; i < (NW * NC) / 4; i += 256) dst[i] = make_float4(0.f, 0.f, 0.f, 0.f);
        }
    }
    for (int i = t; i < 4 * 9 * NC; i += 256) {
        int j = i / (9 * NC);
        int r2 = i % (9 * NC);
        int tap = r2 >> 7, c = r2 & 127;
        sw[i] = w_off[(j * NC + c) * 9 + tap];
    }
    __syncthreads();

    int wid = t >> 5, lane = t & 31;
    for (int it = 0; it < 8; it++) {
        int p = it * 8 + wid;
        float a0 = 0.f, a1 = 0.f, a2 = 0.f, a3 = 0.f;
#pragma unroll
        for (int tap = 0; tap < 9; tap++) {
            int dx = tap % 3 - 1;
            int dy = tap / 3;
            int xx = p + dx;
            if (xx < 0 || xx >= NW) continue;
            float4 xv = *(const float4*)(xin + (dy * NW + xx) * NC + lane * 4);
            float4 w0 = *(const float4*)(sw + (0 * 9 + tap) * NC + lane * 4);
            float4 w1 = *(const float4*)(sw + (1 * 9 + tap) * NC + lane * 4);
            float4 w2 = *(const float4*)(sw + (2 * 9 + tap) * NC + lane * 4);
            float4 w3 = *(const float4*)(sw + (3 * 9 + tap) * NC + lane * 4);
            a0 += xv.x * w0.x + xv.y * w0.y + xv.z * w0.z + xv.w * w0.w;
            a1 += xv.x * w1.x + xv.y * w1.y + xv.z * w1.z + xv.w * w1.w;
            a2 += xv.x * w2.x + xv.y * w2.y + xv.z * w2.z + xv.w * w2.w;
            a3 += xv.x * w3.x + xv.y * w3.y + xv.z * w3.z + xv.w * w3.w;
        }
#pragma unroll
        for (int off = 16; off; off >>= 1) {
            a0 += __shfl_xor_sync(0xffffffffu, a0, off);
            a1 += __shfl_xor_sync(0xffffffffu, a1, off);
            a2 += __shfl_xor_sync(0xffffffffu, a2, off);
            a3 += __shfl_xor_sync(0xffffffffu, a3, off);
        }
        if (lane == 0) {
            float sy = a0 + b_off[0];
            float sx = a1 + b_off[1];
            float s1 = fmaxf(a2 + b_off[2], 0.f) + 1.f;
            float s2 = fmaxf(a3 + b_off[3], 0.f) + 1.f;
            *(float4*)(g_off + ((b * NH + h) * NW + p) * 4) = make_float4(sy, sx, s1, s2);
        }
    }
}

// ---------------------------------------------------------------------------
// Kernel 4: warp-specialized deformable conv.
// grid (2*NH, NB): block = (b, h, half-row of 32 pixels).
// 288 threads: warps 0-7 = consumers (GEMM), warp 8 = producer (sampling).
// Double-buffered s_sm[2][32][132], full/empty mbarriers, producer runs
// up to 2 taps ahead.
// GEMM: channel-paired f32x2 — acc halves = even/odd channel partials.
// ---------------------------------------------------------------------------
__global__ void __launch_bounds__(288, 2) k_main(const float* __restrict__ bias,
                                                 float* __restrict__ out) {
    __shared__ __align__(16) float s_sm[2 * 32 * 132];   // 33.8 KB, 2 buffers
    __shared__ __align__(16) int4   ci_s[32];
    __shared__ __align__(16) float4 cw_s[32];
    __shared__ __align__(8)  unsigned long long mbar[4]; // full0, full1, empty0, empty1

    int h = blockIdx.x >> 1;
    int half = blockIdx.x & 1;
    int b = blockIdx.y;
    int t = threadIdx.x;

    unsigned mb_base = smaddr(&mbar[0]);
    if (t == 0) {
        mb_init(mb_base + 0,  1);   // full0
        mb_init(mb_base + 8,  1);   // full1
        mb_init(mb_base + 16, 8);   // empty0 (one arrive per consumer warp)
        mb_init(mb_base + 24, 8);   // empty1
    }

    unsigned long long acc[16];
#pragma unroll
    for (int i = 0; i < 16; i++) acc[i] = 0ull;

    const float* xb = g_xt + (size_t)b * (NH * NW * NC);
    __syncthreads();

    if (t >= 256) {
        // ================= PRODUCER (warp 8) =================
        int lane = t - 256;
        int pw = half * 32 + lane;
        float4 pr = *(const float4*)(g_off + ((b * NH + h) * NW + pw) * 4);

        for (int k = 0; k < 9; k++) {
            int buf = k & 1;
            if (k >= 2) mb_wait(mb_base + 16 + 8 * buf, ((k >> 1) - 1) & 1);

            // corner math for this lane's pixel
            float sc = (k & 1) ? pr.w : pr.z;
            float py = (float)h + c_BY[k] * sc + pr.x;
            float px = (float)pw + c_BX[k] * sc + pr.y;
            float y0f = floorf(py), x0f = floorf(px);
            float wy = py - y0f, wx = px - x0f;
            int y0 = (int)y0f, x0 = (int)x0f;
            int y1 = y0 + 1, x1 = x0 + 1;
            float w00 = (1.f - wy) * (1.f - wx);
            float w01 = (1.f - wy) * wx;
            float w10 = wy * (1.f - wx);
            float w11 = wy * wx;
            bool vy0 = (y0 >= 0) && (y0 < NH), vy1 = (y1 >= 0) && (y1 < NH);
            bool vx0 = (x0 >= 0) && (x0 < NW), vx1 = (x1 >= 0) && (x1 < NW);
            int cy0 = min(max(y0, 0), NH - 1), cy1 = min(max(y1, 0), NH - 1);
            int cx0 = min(max(x0, 0), NW - 1), cx1 = min(max(x1, 0), NW - 1);
            cw_s[lane] = make_float4((vy0 && vx0) ? w00 : 0.f,
                                     (vy0 && vx1) ? w01 : 0.f,
                                     (vy1 && vx0) ? w10 : 0.f,
                                     (vy1 && vx1) ? w11 : 0.f);
            ci_s[lane] = make_int4((cy0 * NW + cx0) * NC, (cy0 * NW + cx1) * NC,
                                   (cy1 * NW + cx0) * NC, (cy1 * NW + cx1) * NC);
            __syncwarp();

            float* sb = s_sm + buf * 4224;
#pragma unroll 4
            for (int p = 0; p < 32; p++) {
                int4 ci = ci_s[p];
                float4 cw = cw_s[p];
                float4 v00 = *(const float4*)(xb + ci.x + lane * 4);
                float4 v01 = *(const float4*)(xb + ci.y + lane * 4);
                float4 v10 = *(const float4*)(xb + ci.z + lane * 4);
                float4 v11 = *(const float4*)(xb + ci.w + lane * 4);
                float4 s;
                s.x = cw.x * v00.x + cw.y * v01.x + cw.z * v10.x + cw.w * v11.x;
                s.y = cw.x * v00.y + cw.y * v01.y + cw.z * v10.y + cw.w * v11.y;
                s.z = cw.x * v00.z + cw.y * v01.z + cw.z * v10.z + cw.w * v11.z;
                s.w = cw.x * v00.w + cw.y * v01.w + cw.z * v10.w + cw.w * v11.w;
                *(float4*)(sb + p * 132 + lane * 4) = s;
            }
            __syncwarp();
            if (lane == 0) mb_arrive(mb_base + 8 * buf);   // full[buf]
        }
    } else {
        // ================= CONSUMERS (warps 0-7) =================
        int wid = t >> 5;      // pixel group: m = 4*wid .. 4*wid+3
        int oq  = t & 31;      // output quad: o = 4*oq .. 4*oq+3

        for (int k = 0; k < 9; k++) {
            int buf = k & 1;
            mb_wait(mb_base + 8 * buf, (k >> 1) & 1);      // full[buf]

            const float* wk = g_wt2 + k * 16384 + 8 * oq;
            const float* srow = s_sm + buf * 4224 + wid * (4 * 132);
#pragma unroll 8
            for (int c4 = 0; c4 < 32; c4++) {
                const float* wp = wk + c4 * 512;
                ulonglong2 wA01 = *(const ulonglong2*)(wp);
                ulonglong2 wA23 = *(const ulonglong2*)(wp + 4);
                ulonglong2 wB01 = *(const ulonglong2*)(wp + 256);
                ulonglong2 wB23 = *(const ulonglong2*)(wp + 260);
                unsigned long long wA[4] = {wA01.x, wA01.y, wA23.x, wA23.y};
                unsigned long long wB[4] = {wB01.x, wB01.y, wB23.x, wB23.y};
                unsigned long long sA[4], sB[4];
#pragma unroll
                for (int m = 0; m < 4; m++) {
                    ulonglong2 sv = *(const ulonglong2*)(srow + m * 132 + 4 * c4);
                    sA[m] = sv.x;
                    sB[m] = sv.y;
                }
#pragma unroll
                for (int o = 0; o < 4; o++)
#pragma unroll
                    for (int m = 0; m < 4; m++) {
                        asm("fma.rn.f32x2 %0, %1, %2, %0;"
                            : "+l"(acc[o * 4 + m]) : "l"(wA[o]), "l"(sA[m]));
                        asm("fma.rn.f32x2 %0, %1, %2, %0;"
                            : "+l"(acc[o * 4 + m]) : "l"(wB[o]), "l"(sB[m]));
                    }
            }
            if (oq == 0) mb_arrive(mb_base + 16 + 8 * buf);  // empty[buf]
        }
    }

    __syncthreads();   // all taps done; safe to overlay staging onto s_sm

    // stage transposed [o][33] (even+odd channel partial sums combined)
    if (t < 256) {
        int wid = t >> 5, oq = t & 31;
#pragma unroll
        for (int o = 0; o < 4; o++)
#pragma unroll
            for (int m = 0; m < 4; m++) {
                float lo, hi;
                asm("mov.b64 {%0, %1}, %2;" : "=f"(lo), "=f"(hi) : "l"(acc[o * 4 + m]));
                s_sm[(4 * oq + o) * 33 + 4 * wid + m] = lo + hi;
            }
    }
    __syncthreads();

    // coalesced NCHW write
    float* ob = out + (((size_t)b * NC) * NH + h) * NW + half * 32;
    for (int idx = t; idx < NC * 32; idx += 288) {
        int o = idx >> 5, m = idx & 31;
        ob[(size_t)o * (NH * NW) + m] = s_sm[o * 33 + m] + __ldg(bias + o);
    }
}

// ---------------------------------------------------------------------------
extern "C" void kernel_launch(void* const* d_in, const int* in_sizes, int n_in,
                              void* d_out, int out_size) {
    const float* x     = (const float*)d_in[0];
    const float* w_off = (const float*)d_in[1];
    const float* b_off = (const float*)d_in[2];
    const float* w     = (const float*)d_in[3];
    const float* bias  = (const float*)d_in[4];
    float* out = (float*)d_out;

    k_transpose<<<dim3(NB * NH, NC / 32, NW / 32), dim3(32, 8)>>>(x);
    k_wt2<<<(9 * 64 * 256 + 255) / 256, 256>>>(w);

    int off_smem = (3 * NW * NC + 4 * 9 * NC) * (int)sizeof(float);   // 116 KB
    cudaFuncSetAttribute(k_off, cudaFuncAttributeMaxDynamicSharedMemorySize, off_smem);
    k_off<<<dim3(NH, NB), 256, off_smem>>>(w_off, b_off);

    k_main<<<dim3(2 * NH, NB), 288>>>(bias, out);
}